// round 3
// baseline (speedup 1.0000x reference)
#include <cuda_runtime.h>
#include <cuda_bf16.h>

// Problem dims
#define Tt 128
#define Bb 32
#define Ii 256
#define Hh 1024
#define Oo 128
#define BH (Bb*Hh)      // 32768 floats per timestep of h
#define MROWS (Tt*Bb)   // 4096 flattened (t,b) rows
#define GRID_SCAN 128

// Scratch (device globals: no allocations allowed)
__device__ float g_xin[Tt*BH];        // X @ W_in^T, [T,B,H]
__device__ float g_h[(Tt+1)*BH];      // h_all[0..T], [T+1,B,H]
__device__ float g_err[MROWS*Oo];     // err, [T*B,O]
__device__ float g_c[MROWS*Hh];       // c, then (in-place) a, [T*B,H]
__device__ unsigned g_bar;

// ---------------------------------------------------------------------------
// init: copy h0 into g_h[0], reset barrier counter
// ---------------------------------------------------------------------------
__global__ void init_kernel(const float* __restrict__ h0)
{
    int i = blockIdx.x * blockDim.x + threadIdx.x;
    if (i == 0) g_bar = 0u;
    if (i < BH) g_h[i] = h0[i];
}

// ---------------------------------------------------------------------------
// Forward scan: h_{t+1} = tanh(xin_t + h_t @ W_hh^T)
// Persistent kernel: 128 CTAs x 256 threads, CTA c owns j in [8c, 8c+8).
// W_hh rows for the tile live in SMEM for the whole kernel.
// Cross-step h reads bypass L1 (__ldcg); release/acquire via threadfence +
// global atomic barrier. All 128 CTAs are co-resident (<=148 SMs, 1 CTA/SM).
// ---------------------------------------------------------------------------
__global__ void __launch_bounds__(256, 1) scan_fwd(const float* __restrict__ Whh,
                                                   float* __restrict__ hf_out)
{
    __shared__ float Ws[8][1028];   // pad 1028: banks (4*jj + k) % 32, conflict-free
    __shared__ float hs[32][68];    // 64-wide k chunk, pad 68

    int tid = threadIdx.x;
    int jt  = blockIdx.x * 8;

    // One-time load of this CTA's 8 W_hh rows into SMEM
    for (int e = tid; e < 8 * Hh; e += 256)
        Ws[e >> 10][e & 1023] = Whh[(jt + (e >> 10)) * Hh + (e & 1023)];

    int jj  = tid & 7;
    int b   = tid >> 3;
    int myj = jt + jj;
    __syncthreads();

    for (int t = 0; t < Tt; ++t) {
        const float* hcur = g_h + (size_t)t * BH;
        float4 acc4 = make_float4(0.f, 0.f, 0.f, 0.f);  // 4 chains to hide FFMA latency
        float  accx = g_xin[(size_t)t * BH + b * Hh + myj];

        #pragma unroll 1
        for (int kc = 0; kc < Hh; kc += 64) {
            __syncthreads();
            // stage h chunk [32 x 64] cooperatively, L2-coherent loads
            {
                int f  = tid;
                int rb = f >> 4, rk = (f & 15) << 2;
                *(float4*)&hs[rb][rk] = __ldcg((const float4*)&hcur[rb * Hh + kc + rk]);
                f  = tid + 256;
                rb = f >> 4; rk = (f & 15) << 2;
                *(float4*)&hs[rb][rk] = __ldcg((const float4*)&hcur[rb * Hh + kc + rk]);
            }
            __syncthreads();
            #pragma unroll
            for (int k = 0; k < 64; k += 4) {
                float4 hv = *(float4*)&hs[b][k];
                float4 wv = *(float4*)&Ws[jj][kc + k];
                acc4.x += hv.x * wv.x;
                acc4.y += hv.y * wv.y;
                acc4.z += hv.z * wv.z;
                acc4.w += hv.w * wv.w;
            }
        }
        float hn = tanhf(accx + (acc4.x + acc4.y) + (acc4.z + acc4.w));
        g_h[(size_t)(t + 1) * BH + b * Hh + myj] = hn;
        if (t == Tt - 1) hf_out[b * Hh + myj] = hn;

        // global barrier (release -> arrive -> spin -> acquire)
        __threadfence();
        __syncthreads();
        if (tid == 0) {
            atomicAdd(&g_bar, 1u);
            unsigned tgt = (unsigned)(t + 1) * GRID_SCAN;
            while (*((volatile unsigned*)&g_bar) < tgt) { }
            __threadfence();
        }
        __syncthreads();
    }
}

// ---------------------------------------------------------------------------
// Backward scan (elementwise, fully parallel over (b,j)):
//   a_t = c_t + diag(W_hh)[j] * (1 - h_all[t+1]^2) * a_{t+1}, in place in g_c
// ---------------------------------------------------------------------------
__global__ void scan_bwd(const float* __restrict__ Whh)
{
    int flat = blockIdx.x * blockDim.x + threadIdx.x;  // 0..BH-1
    int j = flat & (Hh - 1);
    float dw = Whh[j * Hh + j];
    float a = g_c[(size_t)(Tt - 1) * BH + flat];
    for (int t = Tt - 2; t >= 0; --t) {
        float h   = g_h[(size_t)(t + 1) * BH + flat];
        float php = 1.f - h * h;
        a = g_c[(size_t)t * BH + flat] + dw * php * a;
        g_c[(size_t)t * BH + flat] = a;
    }
}

// ---------------------------------------------------------------------------
// Generic tiled fp32 GEMM: C[m,n] = scale * sum_k A[m*sAm + k*sAk]*B[n*sBn + k*sBk]
// Tiles 64x64x16, 256 threads, 4x4 micro-tile per thread.
// AKC/BKC: true if the k-stride of that operand is 1 (pick coalesced loader).
// EPI: 0 plain store; 1 store + err = acc - Q0 into P1; 2 store acc*(1-Q0^2).
// All M,N divisible by 64 and K by 16 in this problem (no bounds checks).
// ---------------------------------------------------------------------------
template<bool KC>
__device__ __forceinline__ void load_tile(float (*S)[68], const float* __restrict__ P,
                                          int sRow, int sK, int row0, int k0, int tid)
{
    if (KC) {
        // k contiguous: float4 along k, transpose-scatter into S[k][row]
        int r  = tid >> 2;
        int kk = (tid & 3) << 2;
        float4 v = *(const float4*)&P[(size_t)(row0 + r) * sRow + k0 + kk];
        S[kk + 0][r] = v.x; S[kk + 1][r] = v.y; S[kk + 2][r] = v.z; S[kk + 3][r] = v.w;
    } else {
        // row contiguous (sRow==1): float4 along row, direct store
        int kk = tid >> 4;
        int r  = (tid & 15) << 2;
        *(float4*)&S[kk][r] = *(const float4*)&P[(size_t)(k0 + kk) * sK + row0 + r];
    }
}

template<bool AKC, bool BKC, int EPI>
__global__ void __launch_bounds__(256) gemm64(const float* __restrict__ A, int sAm, int sAk,
                                              const float* __restrict__ B, int sBn, int sBk,
                                              int N, int K, float scale,
                                              float* __restrict__ P0, float* __restrict__ P1,
                                              const float* __restrict__ Q0)
{
    __shared__ float As[16][68];
    __shared__ float Bs[16][68];
    int tid = threadIdx.x;
    int m0 = blockIdx.y * 64, n0 = blockIdx.x * 64;
    int ty = tid >> 4, tx = tid & 15;

    float acc[4][4] = {};
    for (int k0 = 0; k0 < K; k0 += 16) {
        __syncthreads();
        load_tile<AKC>(As, A, sAm, sAk, m0, k0, tid);
        load_tile<BKC>(Bs, B, sBn, sBk, n0, k0, tid);
        __syncthreads();
        #pragma unroll
        for (int kk = 0; kk < 16; ++kk) {
            float4 a = *(float4*)&As[kk][ty << 2];
            float4 b = *(float4*)&Bs[kk][tx << 2];
            acc[0][0] += a.x * b.x; acc[0][1] += a.x * b.y; acc[0][2] += a.x * b.z; acc[0][3] += a.x * b.w;
            acc[1][0] += a.y * b.x; acc[1][1] += a.y * b.y; acc[1][2] += a.y * b.z; acc[1][3] += a.y * b.w;
            acc[2][0] += a.z * b.x; acc[2][1] += a.z * b.y; acc[2][2] += a.z * b.z; acc[2][3] += a.z * b.w;
            acc[3][0] += a.w * b.x; acc[3][1] += a.w * b.y; acc[3][2] += a.w * b.z; acc[3][3] += a.w * b.w;
        }
    }
    #pragma unroll
    for (int i = 0; i < 4; ++i) {
        int m = m0 + (ty << 2) + i;
        #pragma unroll
        for (int jx = 0; jx < 4; ++jx) {
            int n = n0 + (tx << 2) + jx;
            float v = acc[i][jx] * scale;
            size_t idx = (size_t)m * N + n;
            if (EPI == 0) {
                P0[idx] = v;
            } else if (EPI == 1) {          // O -> ys, err = O - target
                P0[idx] = v;
                P1[idx] = v - Q0[idx];
            } else {                        // c = L * (1 - hnew^2)
                float h = Q0[idx];
                P0[idx] = v * (1.f - h * h);
            }
        }
    }
}

// ---------------------------------------------------------------------------
// Launch sequence (graph-capturable: kernel launches only)
// ---------------------------------------------------------------------------
extern "C" void kernel_launch(void* const* d_in, const int* in_sizes, int n_in,
                              void* d_out, int out_size)
{
    const float* x      = (const float*)d_in[0];  // [T,B,I]
    const float* target = (const float*)d_in[1];  // [T,B,O]
    const float* h0     = (const float*)d_in[2];  // [B,H]
    const float* W_in   = (const float*)d_in[3];  // [H,I]
    const float* W_hh   = (const float*)d_in[4];  // [H,H]
    const float* W_out  = (const float*)d_in[5];  // [O,H]

    float* out   = (float*)d_out;
    float* ys    = out;                                   // [T*B, O]
    float* hf    = out + (size_t)MROWS * Oo;              // [B,H]
    float* gwout = hf + BH;                               // [O,H]
    float* gwih  = gwout + (size_t)Oo * Hh;               // [H,I]
    float* gwhh  = gwih + (size_t)Hh * Ii;                // [H,H]

    float *p_xin, *p_h, *p_err, *p_c;
    cudaGetSymbolAddress((void**)&p_xin, g_xin);
    cudaGetSymbolAddress((void**)&p_h,   g_h);
    cudaGetSymbolAddress((void**)&p_err, g_err);
    cudaGetSymbolAddress((void**)&p_c,   g_c);

    // 1. Xin = X @ W_in^T            [4096,1024], K=256  (DOT)
    gemm64<true, true, 0><<<dim3(Hh / 64, MROWS / 64), 256>>>(
        x, Ii, 1, W_in, Ii, 1, Hh, Ii, 1.f, p_xin, nullptr, nullptr);

    // 2. init h_all[0] + barrier reset
    init_kernel<<<GRID_SCAN, 256>>>(h0);

    // 3. forward scan (persistent), writes h_all[1..T] and h_f
    scan_fwd<<<GRID_SCAN, 256>>>(W_hh, hf);

    // 4. O = Hnew @ W_out^T -> ys; err = O - target      [4096,128], K=1024 (DOT)
    gemm64<true, true, 1><<<dim3(Oo / 64, MROWS / 64), 256>>>(
        p_h + BH, Hh, 1, W_out, Hh, 1, Oo, Hh, 1.f, ys, p_err, target);

    // 5. c = (err @ W_out) * (1 - hnew^2)                [4096,1024], K=128 (NN)
    gemm64<true, false, 2><<<dim3(Hh / 64, MROWS / 64), 256>>>(
        p_err, Oo, 1, W_out, 1, Hh, Hh, Oo, 1.f, p_c, nullptr, p_h + BH);

    // 6. backward scan: c -> a (in place)
    scan_bwd<<<BH / 256, 256>>>(W_hh);

    // 7. g_wout = (1/B) * err^T @ Hnew                   [128,1024], K=4096 (OUTER)
    gemm64<false, false, 0><<<dim3(Hh / 64, Oo / 64), 256>>>(
        p_err, 1, Oo, p_h + BH, 1, Hh, Hh, MROWS, 1.f / Bb, gwout, nullptr, nullptr);

    // 8. g_wih = (1e-3/B) * a^T @ X                      [1024,256], K=4096 (OUTER)
    gemm64<false, false, 0><<<dim3(Ii / 64, Hh / 64), 256>>>(
        p_c, 1, Hh, x, 1, Ii, Ii, MROWS, 1e-3f / Bb, gwih, nullptr, nullptr);

    // 9. g_whh = (1e-5/B) * a^T @ Hprev                  [1024,1024], K=4096 (OUTER)
    gemm64<false, false, 0><<<dim3(Hh / 64, Hh / 64), 256>>>(
        p_c, 1, Hh, p_h, 1, Hh, Hh, MROWS, 1e-5f / Bb, gwhh, nullptr, nullptr);
}

// round 6
// speedup vs baseline: 1.3519x; 1.3519x over previous
#include <cuda_runtime.h>
#include <cuda_bf16.h>
#include <cstdint>

// Problem dims
#define Tt 128
#define Bb 32
#define Ii 256
#define Hh 1024
#define Oo 128
#define BH (Bb*Hh)      // 32768 floats per timestep of h
#define MROWS (Tt*Bb)   // 4096 flattened (t,b) rows
#define GRID_SCAN 128
#define HPAD 1028       // padded row stride (floats) for bank-conflict-free smem

// Scratch (device globals: no allocations allowed)
__device__ float g_xin[Tt*BH];        // X @ W_in^T, [T,B,H]
__device__ float g_h[(Tt+1)*BH];      // h_all[0..T], [T+1,B,H]
__device__ float g_err[MROWS*Oo];     // err, [T*B,O]
__device__ float g_c[MROWS*Hh];       // c, then (in-place) a, [T*B,H]
__device__ unsigned g_bar;

// ---------------------------------------------------------------------------
// cp.async helper (LDGSTS .cg: bypasses L1 -> coherent with other SMs' stores)
// ---------------------------------------------------------------------------
__device__ __forceinline__ void cp16(uint32_t saddr, const void* gptr)
{
    asm volatile("cp.async.cg.shared.global [%0], [%1], 16;\n" :: "r"(saddr), "l"(gptr));
}

// ---------------------------------------------------------------------------
// zero_kernel: grid-stride zero of split-K targets + barrier reset
// init_kernel: copy h0 into g_h[0]
// ---------------------------------------------------------------------------
__global__ void zero_kernel(float* __restrict__ p, int n)
{
    int i = blockIdx.x * blockDim.x + threadIdx.x;
    if (i == 0) g_bar = 0u;
    for (; i < n; i += gridDim.x * blockDim.x) p[i] = 0.f;
}

__global__ void init_kernel(const float* __restrict__ h0)
{
    int i = blockIdx.x * blockDim.x + threadIdx.x;
    if (i < BH) g_h[i] = h0[i];
}

// ---------------------------------------------------------------------------
// Forward scan: h_{t+1} = tanh(xin_t + h_t @ W_hh^T)
// Persistent: 128 CTAs x 256 thr, CTA c owns j in [8c,8c+8). W rows in SMEM
// for the whole kernel. Per step: stage FULL h_t (32x1024) into SMEM via
// 32 cp.async.cg per thread (high MLP, one exposed latency), one sync,
// then a sync-free FFMA loop. Global barrier between steps.
// Dynamic smem: Ws[8*HPAD] + Hs[32*HPAD] = 164,480 B  (1 CTA/SM; 128<=148)
// ---------------------------------------------------------------------------
__global__ void __launch_bounds__(256, 1) scan_fwd(const float* __restrict__ Whh,
                                                   float* __restrict__ hf_out)
{
    extern __shared__ float sm[];
    float* Ws = sm;                 // [8][HPAD]
    float* Hs = sm + 8 * HPAD;      // [32][HPAD]

    int tid = threadIdx.x;
    int jt  = blockIdx.x * 8;

    // One-time: this CTA's 8 W_hh rows into SMEM
    for (int e = tid; e < 8 * Hh; e += 256)
        Ws[(e >> 10) * HPAD + (e & 1023)] = Whh[(size_t)(jt + (e >> 10)) * Hh + (e & 1023)];

    int jj  = tid & 7;
    int b   = tid >> 3;
    int myj = jt + jj;
    const float* wrow = Ws + jj * HPAD;
    const float* hrow = Hs + b  * HPAD;
    uint32_t hs_base = (uint32_t)__cvta_generic_to_shared(Hs);
    __syncthreads();

    for (int t = 0; t < Tt; ++t) {
        const float* hcur = g_h + (size_t)t * BH;

        // Stage full h_t: 8192 float4 over 256 threads = 32 cp.async each.
        #pragma unroll
        for (int r = 0; r < 32; ++r) {
            int f = tid + (r << 8);          // float4 index
            int i = f << 2;                  // element index
            int bb = i >> 10, k = i & 1023;
            cp16(hs_base + (((bb * HPAD) + k) << 2), hcur + i);
        }
        asm volatile("cp.async.commit_group;\n");
        float accx = g_xin[(size_t)t * BH + b * Hh + myj];   // overlap with cp.async
        asm volatile("cp.async.wait_group 0;\n" ::: "memory");
        __syncthreads();

        // Dot product: 1024 FMAs, 4 chains, no syncs.
        float4 acc4 = make_float4(0.f, 0.f, 0.f, 0.f);
        #pragma unroll 1
        for (int kc = 0; kc < Hh; kc += 128) {
            #pragma unroll
            for (int k = 0; k < 128; k += 4) {
                float4 hv = *(const float4*)&hrow[kc + k];
                float4 wv = *(const float4*)&wrow[kc + k];
                acc4.x += hv.x * wv.x;
                acc4.y += hv.y * wv.y;
                acc4.z += hv.z * wv.z;
                acc4.w += hv.w * wv.w;
            }
        }
        float hn = tanhf(accx + (acc4.x + acc4.y) + (acc4.z + acc4.w));
        __stcg(&g_h[(size_t)(t + 1) * BH + b * Hh + myj], hn);
        if (t == Tt - 1) {
            hf_out[b * Hh + myj] = hn;
            break;                            // kernel end publishes final state
        }

        // Global barrier: release -> arrive -> spin -> acquire. Hs fully
        // consumed above, so next step's cp.async can't race it.
        __threadfence();
        __syncthreads();
        if (tid == 0) {
            atomicAdd(&g_bar, 1u);
            unsigned tgt = (unsigned)(t + 1) * GRID_SCAN;
            while (*((volatile unsigned*)&g_bar) < tgt) { }
            __threadfence();
        }
        __syncthreads();
    }
}

// ---------------------------------------------------------------------------
// Backward scan (elementwise, parallel over (b,j)):
//   a_t = c_t + diag(W_hh)[j] * (1 - h_all[t+1]^2) * a_{t+1}, in place in g_c
// ---------------------------------------------------------------------------
__global__ void scan_bwd(const float* __restrict__ Whh)
{
    int flat = blockIdx.x * blockDim.x + threadIdx.x;  // 0..BH-1
    int j = flat & (Hh - 1);
    float dw = Whh[(size_t)j * Hh + j];
    float a = g_c[(size_t)(Tt - 1) * BH + flat];
    for (int t = Tt - 2; t >= 0; --t) {
        float h   = g_h[(size_t)(t + 1) * BH + flat];
        float php = 1.f - h * h;
        a = g_c[(size_t)t * BH + flat] + dw * php * a;
        g_c[(size_t)t * BH + flat] = a;
    }
}

// ---------------------------------------------------------------------------
// Tiled fp32 GEMM, double-buffered: C[m,n] = scale * sum_k A[..]*B[..]
// 64x64 tile, 256 threads, 4x4 micro-tile. One __syncthreads per k-iter;
// next tile is loaded to registers while computing on the current smem buf.
// SPLITK: blockIdx.z selects a K-chunk of length Kc; ATOMIC epilogue adds
// partials into a pre-zeroed output (order-nondeterministic in last bits only).
// EPI: 0 plain/atomic store; 1 store + err=acc-Q0 into P1; 2 store acc*(1-Q0^2).
// ---------------------------------------------------------------------------
template<bool KC>
__device__ __forceinline__ float4 load_frag(const float* __restrict__ P,
                                            int sRow, int sK, int row0, int k0, int tid)
{
    if (KC) {  // k contiguous
        int r  = tid >> 2;
        int kk = (tid & 3) << 2;
        return *(const float4*)&P[(size_t)(row0 + r) * sRow + k0 + kk];
    } else {   // row contiguous
        int kk = tid >> 4;
        int r  = (tid & 15) << 2;
        return *(const float4*)&P[(size_t)(k0 + kk) * sK + row0 + r];
    }
}
template<bool KC>
__device__ __forceinline__ void store_frag(float (*S)[68], float4 v, int tid)
{
    if (KC) {
        int r  = tid >> 2;
        int kk = (tid & 3) << 2;
        S[kk + 0][r] = v.x; S[kk + 1][r] = v.y; S[kk + 2][r] = v.z; S[kk + 3][r] = v.w;
    } else {
        int kk = tid >> 4;
        int r  = (tid & 15) << 2;
        *(float4*)&S[kk][r] = v;
    }
}

template<bool AKC, bool BKC, int EPI, bool ATOMIC>
__global__ void __launch_bounds__(256) gemm64(const float* __restrict__ A, int sAm, int sAk,
                                              const float* __restrict__ B, int sBn, int sBk,
                                              int N, int Kc, float scale,
                                              float* __restrict__ P0, float* __restrict__ P1,
                                              const float* __restrict__ Q0)
{
    __shared__ float As[2][16][68];
    __shared__ float Bs[2][16][68];
    int tid = threadIdx.x;
    int m0 = blockIdx.y * 64, n0 = blockIdx.x * 64;
    int kbeg = blockIdx.z * Kc, kend = kbeg + Kc;
    int ty = tid >> 4, tx = tid & 15;

    store_frag<AKC>(As[0], load_frag<AKC>(A, sAm, sAk, m0, kbeg, tid), tid);
    store_frag<BKC>(Bs[0], load_frag<BKC>(B, sBn, sBk, n0, kbeg, tid), tid);
    __syncthreads();

    float acc[4][4] = {};
    int p = 0;
    for (int k0 = kbeg; k0 < kend; k0 += 16) {
        bool more = (k0 + 16) < kend;
        float4 an, bn;
        if (more) {
            an = load_frag<AKC>(A, sAm, sAk, m0, k0 + 16, tid);
            bn = load_frag<BKC>(B, sBn, sBk, n0, k0 + 16, tid);
        }
        #pragma unroll
        for (int kk = 0; kk < 16; ++kk) {
            float4 a = *(float4*)&As[p][kk][ty << 2];
            float4 b = *(float4*)&Bs[p][kk][tx << 2];
            acc[0][0] += a.x * b.x; acc[0][1] += a.x * b.y; acc[0][2] += a.x * b.z; acc[0][3] += a.x * b.w;
            acc[1][0] += a.y * b.x; acc[1][1] += a.y * b.y; acc[1][2] += a.y * b.z; acc[1][3] += a.y * b.w;
            acc[2][0] += a.z * b.x; acc[2][1] += a.z * b.y; acc[2][2] += a.z * b.z; acc[2][3] += a.z * b.w;
            acc[3][0] += a.w * b.x; acc[3][1] += a.w * b.y; acc[3][2] += a.w * b.z; acc[3][3] += a.w * b.w;
        }
        if (more) {
            store_frag<AKC>(As[p ^ 1], an, tid);
            store_frag<BKC>(Bs[p ^ 1], bn, tid);
            __syncthreads();
            p ^= 1;
        }
    }

    #pragma unroll
    for (int i = 0; i < 4; ++i) {
        int m = m0 + (ty << 2) + i;
        #pragma unroll
        for (int jx = 0; jx < 4; ++jx) {
            int n = n0 + (tx << 2) + jx;
            float v = acc[i][jx] * scale;
            size_t idx = (size_t)m * N + n;
            if (ATOMIC) {
                atomicAdd(&P0[idx], v);
            } else if (EPI == 0) {
                P0[idx] = v;
            } else if (EPI == 1) {          // O -> ys, err = O - target
                P0[idx] = v;
                P1[idx] = v - Q0[idx];
            } else {                        // c = L * (1 - hnew^2)
                float h = Q0[idx];
                P0[idx] = v * (1.f - h * h);
            }
        }
    }
}

// ---------------------------------------------------------------------------
// Launch sequence (graph-capturable: kernel launches only)
// ---------------------------------------------------------------------------
extern "C" void kernel_launch(void* const* d_in, const int* in_sizes, int n_in,
                              void* d_out, int out_size)
{
    const float* x      = (const float*)d_in[0];  // [T,B,I]
    const float* target = (const float*)d_in[1];  // [T,B,O]
    const float* h0     = (const float*)d_in[2];  // [B,H]
    const float* W_in   = (const float*)d_in[3];  // [H,I]
    const float* W_hh   = (const float*)d_in[4];  // [H,H]
    const float* W_out  = (const float*)d_in[5];  // [O,H]

    float* out   = (float*)d_out;
    float* ys    = out;                                   // [T*B, O]
    float* hf    = out + (size_t)MROWS * Oo;              // [B,H]
    float* gwout = hf + BH;                               // [O,H]
    float* gwih  = gwout + (size_t)Oo * Hh;               // [H,I]
    float* gwhh  = gwih + (size_t)Hh * Ii;                // [H,H]

    float *p_xin, *p_h, *p_err, *p_c;
    cudaGetSymbolAddress((void**)&p_xin, g_xin);
    cudaGetSymbolAddress((void**)&p_h,   g_h);
    cudaGetSymbolAddress((void**)&p_err, g_err);
    cudaGetSymbolAddress((void**)&p_c,   g_c);

    const int SMEM_SCAN = (8 + Bb) * HPAD * 4;   // 164,480 B dynamic
    cudaFuncSetAttribute(scan_fwd, cudaFuncAttributeMaxDynamicSharedMemorySize, SMEM_SCAN);

    // 0. zero split-K accumulation targets (gwout..gwhh contiguous) + g_bar
    // (kNumZero, NOT "NZERO": glibc <limits.h> defines NZERO=20 on the GPU host)
    const int kNumZero = Oo * Hh + Hh * Ii + Hh * Hh;   // 1,441,792 floats
    zero_kernel<<<256, 256>>>(gwout, kNumZero);

    // 1. Xin = X @ W_in^T            [4096,1024], K=256  (DOT)
    gemm64<true, true, 0, false><<<dim3(Hh / 64, MROWS / 64, 1), 256>>>(
        x, Ii, 1, W_in, Ii, 1, Hh, Ii, 1.f, p_xin, nullptr, nullptr);

    // 2. init h_all[0]
    init_kernel<<<BH / 256, 256>>>(h0);

    // 3. forward scan (persistent), writes h_all[1..T] and h_f
    scan_fwd<<<GRID_SCAN, 256, SMEM_SCAN>>>(W_hh, hf);

    // 4. O = Hnew @ W_out^T -> ys; err = O - target      [4096,128], K=1024 (DOT)
    gemm64<true, true, 1, false><<<dim3(Oo / 64, MROWS / 64, 1), 256>>>(
        p_h + BH, Hh, 1, W_out, Hh, 1, Oo, Hh, 1.f, ys, p_err, target);

    // 5. c = (err @ W_out) * (1 - hnew^2)                [4096,1024], K=128 (NN)
    gemm64<true, false, 2, false><<<dim3(Hh / 64, MROWS / 64, 1), 256>>>(
        p_err, Oo, 1, W_out, 1, Hh, Hh, Oo, 1.f, p_c, nullptr, p_h + BH);

    // 6. backward scan: c -> a (in place)
    scan_bwd<<<BH / 256, 256>>>(W_hh);

    // 7. g_wout = (1/B) * err^T @ Hnew       [128,1024], K=4096, split 8 -> 256 CTAs
    gemm64<false, false, 0, true><<<dim3(Hh / 64, Oo / 64, 8), 256>>>(
        p_err, 1, Oo, p_h + BH, 1, Hh, Hh, MROWS / 8, 1.f / Bb, gwout, nullptr, nullptr);

    // 8. g_wih = (1e-3/B) * a^T @ X          [1024,256], K=4096, split 4 -> 256 CTAs
    gemm64<false, false, 0, true><<<dim3(Ii / 64, Hh / 64, 4), 256>>>(
        p_c, 1, Hh, x, 1, Ii, Ii, MROWS / 4, 1e-3f / Bb, gwih, nullptr, nullptr);

    // 9. g_whh = (1e-5/B) * a^T @ Hprev      [1024,1024], K=4096, split 2 -> 512 CTAs
    gemm64<false, false, 0, true><<<dim3(Hh / 64, Hh / 64, 2), 256>>>(
        p_c, 1, Hh, p_h, 1, Hh, Hh, MROWS / 2, 1e-5f / Bb, gwhh, nullptr, nullptr);
}

// round 7
// speedup vs baseline: 1.5029x; 1.1117x over previous
#include <cuda_runtime.h>
#include <cuda_bf16.h>
#include <cstdint>

// Problem dims
#define Tt 128
#define Bb 32
#define Ii 256
#define Hh 1024
#define Oo 128
#define BH (Bb*Hh)      // 32768 floats per timestep of h
#define MROWS (Tt*Bb)   // 4096 flattened (t,b) rows
#define GRID_SCAN 128
#define HPAD 1028       // padded row stride (floats) for bank-conflict-free smem

// Scratch (device globals: no allocations allowed)
__device__ float g_xin[Tt*BH];        // X @ W_in^T, [T,B,H]
__device__ float g_h[(Tt+1)*BH];      // h_all[0..T], [T+1,B,H]
__device__ float g_err[MROWS*Oo];     // err, [T*B,O]
__device__ float g_c[MROWS*Hh];       // c, then (in-place) a, [T*B,H]
__device__ unsigned g_bar;

// ---------------------------------------------------------------------------
// Packed fp32x2 FMA (Blackwell FFMA2: 2 fp32 FMAs per instruction)
// ---------------------------------------------------------------------------
__device__ __forceinline__ unsigned long long ffma2_(unsigned long long a,
                                                     unsigned long long b,
                                                     unsigned long long c)
{
    unsigned long long d;
    asm("fma.rn.f32x2 %0, %1, %2, %3;" : "=l"(d) : "l"(a), "l"(b), "l"(c));
    return d;
}
__device__ __forceinline__ unsigned long long dup2_(float x)
{
    unsigned long long d;
    asm("mov.b64 %0, {%1, %1};" : "=l"(d) : "f"(x));
    return d;
}
union F4U { float4 f; unsigned long long u[2]; float s[4]; };
union U2F { unsigned long long u; float2 f; };

// ---------------------------------------------------------------------------
// cp.async helper (LDGSTS .cg: bypasses L1 -> coherent with other SMs' stores)
// ---------------------------------------------------------------------------
__device__ __forceinline__ void cp16(uint32_t saddr, const void* gptr)
{
    asm volatile("cp.async.cg.shared.global [%0], [%1], 16;\n" :: "r"(saddr), "l"(gptr));
}

// ---------------------------------------------------------------------------
// zero_kernel: grid-stride zero of split-K targets + barrier reset
// init_kernel: copy h0 into g_h[0]
// ---------------------------------------------------------------------------
__global__ void zero_kernel(float* __restrict__ p, int n)
{
    int i = blockIdx.x * blockDim.x + threadIdx.x;
    if (i == 0) g_bar = 0u;
    for (; i < n; i += gridDim.x * blockDim.x) p[i] = 0.f;
}

__global__ void init_kernel(const float* __restrict__ h0)
{
    int i = blockIdx.x * blockDim.x + threadIdx.x;
    if (i < BH) g_h[i] = h0[i];
}

// ---------------------------------------------------------------------------
// Forward scan: h_{t+1} = tanh(xin_t + h_t @ W_hh^T)
// Persistent: 128 CTAs x 256 thr, CTA c owns j in [8c,8c+8). W rows in SMEM.
// Per step: h_t staged in 4 k-chunks (cp.async commit groups); compute on
// chunk c overlaps transfer of chunks c+1..3. Inner product in fp32x2.
// Dynamic smem: Ws[8*HPAD] + Hs[32*HPAD] = 164,480 B  (1 CTA/SM; 128<=148)
// ---------------------------------------------------------------------------
__global__ void __launch_bounds__(256, 1) scan_fwd(const float* __restrict__ Whh,
                                                   float* __restrict__ hf_out)
{
    extern __shared__ float sm[];
    float* Ws = sm;                 // [8][HPAD]
    float* Hs = sm + 8 * HPAD;      // [32][HPAD]

    int tid = threadIdx.x;
    int jt  = blockIdx.x * 8;

    // One-time: this CTA's 8 W_hh rows into SMEM
    for (int e = tid; e < 8 * Hh; e += 256)
        Ws[(e >> 10) * HPAD + (e & 1023)] = Whh[(size_t)(jt + (e >> 10)) * Hh + (e & 1023)];

    int jj  = tid & 7;
    int b   = tid >> 3;
    int myj = jt + jj;
    const float* wrow = Ws + jj * HPAD;
    const float* hrow = Hs + b  * HPAD;
    uint32_t hs_base = (uint32_t)__cvta_generic_to_shared(Hs);
    __syncthreads();

    for (int t = 0; t < Tt; ++t) {
        const float* hcur = g_h + (size_t)t * BH;

        // Stage h_t in 4 chunks of k in [256c, 256c+256): per chunk 2048
        // float4 over 256 threads = 8 cp.async each, one commit group.
        #pragma unroll
        for (int c = 0; c < 4; ++c) {
            #pragma unroll
            for (int r = 0; r < 8; ++r) {
                int fl = tid + (r << 8);            // 0..2047 within chunk
                int bb = fl >> 6;                   // 64 float4 per b-row
                int k  = (c << 8) + ((fl & 63) << 2);
                cp16(hs_base + ((bb * HPAD + k) << 2), hcur + bb * Hh + k);
            }
            asm volatile("cp.async.commit_group;\n");
        }
        float accx = g_xin[(size_t)t * BH + b * Hh + myj];   // overlaps transfers

        unsigned long long acc01 = 0ull, acc23 = 0ull;       // == (0.f, 0.f)

        // chunk c compute (64 float4 = 256 k): fp32x2 FMAs on natural pairs
        #define SCAN_CHUNK(c)                                                   \
        {                                                                       \
            __syncthreads();                                                    \
            _Pragma("unroll")                                                   \
            for (int k4 = 0; k4 < 64; ++k4) {                                   \
                int k = ((c) << 8) + (k4 << 2);                                 \
                F4U hv, wv;                                                     \
                hv.f = *(const float4*)&hrow[k];                                \
                wv.f = *(const float4*)&wrow[k];                                \
                acc01 = ffma2_(hv.u[0], wv.u[0], acc01);                        \
                acc23 = ffma2_(hv.u[1], wv.u[1], acc23);                        \
            }                                                                   \
        }
        asm volatile("cp.async.wait_group 3;\n" ::: "memory"); SCAN_CHUNK(0)
        asm volatile("cp.async.wait_group 2;\n" ::: "memory"); SCAN_CHUNK(1)
        asm volatile("cp.async.wait_group 1;\n" ::: "memory"); SCAN_CHUNK(2)
        asm volatile("cp.async.wait_group 0;\n" ::: "memory"); SCAN_CHUNK(3)
        #undef SCAN_CHUNK

        U2F s01, s23; s01.u = acc01; s23.u = acc23;
        float hn = tanhf(accx + (s01.f.x + s01.f.y) + (s23.f.x + s23.f.y));
        __stcg(&g_h[(size_t)(t + 1) * BH + b * Hh + myj], hn);
        if (t == Tt - 1) {
            hf_out[b * Hh + myj] = hn;
            break;                            // kernel end publishes final state
        }

        // Global barrier: release -> arrive -> spin -> acquire.
        __threadfence();
        __syncthreads();
        if (tid == 0) {
            atomicAdd(&g_bar, 1u);
            unsigned tgt = (unsigned)(t + 1) * GRID_SCAN;
            while (*((volatile unsigned*)&g_bar) < tgt) { }
            __threadfence();
        }
        __syncthreads();
    }
}

// ---------------------------------------------------------------------------
// Backward scan (elementwise, parallel over (b,j)):
//   a_t = c_t + diag(W_hh)[j] * (1 - h_all[t+1]^2) * a_{t+1}, in place in g_c
// ---------------------------------------------------------------------------
__global__ void scan_bwd(const float* __restrict__ Whh)
{
    int flat = blockIdx.x * blockDim.x + threadIdx.x;  // 0..BH-1
    int j = flat & (Hh - 1);
    float dw = Whh[(size_t)j * Hh + j];
    float a = g_c[(size_t)(Tt - 1) * BH + flat];
    for (int t = Tt - 2; t >= 0; --t) {
        float h   = g_h[(size_t)(t + 1) * BH + flat];
        float php = 1.f - h * h;
        a = g_c[(size_t)t * BH + flat] + dw * php * a;
        g_c[(size_t)t * BH + flat] = a;
    }
}

// ---------------------------------------------------------------------------
// Tiled fp32 GEMM, double-buffered, fp32x2 inner: C[m,n] = scale*sum_k A*B
// Tile TM x 64 (TM = 64 or 128), 256 threads, (TM/16) x 4 micro-tile per
// thread as m-pairs in packed f32x2. One __syncthreads per k-iter.
// SPLITK via blockIdx.z (chunk length Kc) + ATOMIC epilogue into zeroed out.
// EPI: 0 plain store; 1 store + err=acc-Q0 into P1; 2 store acc*(1-Q0^2).
// ---------------------------------------------------------------------------
template<int TM, bool AKC, bool BKC, int EPI, bool ATOMIC>
__global__ void __launch_bounds__(256) gemmT(const float* __restrict__ A, int sAm, int sAk,
                                             const float* __restrict__ B, int sBn, int sBk,
                                             int N, int Kc, float scale,
                                             float* __restrict__ P0, float* __restrict__ P1,
                                             const float* __restrict__ Q0)
{
    constexpr int MI  = TM / 16;     // per-thread m extent (4 or 8)
    constexpr int NLA = TM / 64;     // A-loader iterations (1 or 2)
    __shared__ float As[2][16][TM + 4];
    __shared__ float Bs[2][16][68];
    int tid = threadIdx.x;
    int m0 = blockIdx.y * TM, n0 = blockIdx.x * 64;
    int kbeg = blockIdx.z * Kc, kend = kbeg + Kc;
    int ty = tid >> 4, tx = tid & 15;

    float4 aP[NLA], bP;
    auto loadA = [&](int k0) {
        #pragma unroll
        for (int it = 0; it < NLA; ++it) {
            int f = tid + (it << 8);
            if (AKC) { int r = f >> 2, kk = (f & 3) << 2;
                aP[it] = *(const float4*)&A[(size_t)(m0 + r) * sAm + k0 + kk]; }
            else { int kk = f / (TM / 4), r = (f % (TM / 4)) << 2;
                aP[it] = *(const float4*)&A[(size_t)(k0 + kk) * sAk + m0 + r]; }
        }
    };
    auto storeA = [&](int p) {
        #pragma unroll
        for (int it = 0; it < NLA; ++it) {
            int f = tid + (it << 8);
            if (AKC) { int r = f >> 2, kk = (f & 3) << 2;
                As[p][kk][r] = aP[it].x; As[p][kk+1][r] = aP[it].y;
                As[p][kk+2][r] = aP[it].z; As[p][kk+3][r] = aP[it].w; }
            else { int kk = f / (TM / 4), r = (f % (TM / 4)) << 2;
                *(float4*)&As[p][kk][r] = aP[it]; }
        }
    };
    auto loadB = [&](int k0) {
        if (BKC) { int r = tid >> 2, kk = (tid & 3) << 2;
            bP = *(const float4*)&B[(size_t)(n0 + r) * sBn + k0 + kk]; }
        else { int kk = tid >> 4, r = (tid & 15) << 2;
            bP = *(const float4*)&B[(size_t)(k0 + kk) * sBk + n0 + r]; }
    };
    auto storeB = [&](int p) {
        if (BKC) { int r = tid >> 2, kk = (tid & 3) << 2;
            Bs[p][kk][r] = bP.x; Bs[p][kk+1][r] = bP.y;
            Bs[p][kk+2][r] = bP.z; Bs[p][kk+3][r] = bP.w; }
        else { int kk = tid >> 4, r = (tid & 15) << 2;
            *(float4*)&Bs[p][kk][r] = bP; }
    };

    loadA(kbeg); loadB(kbeg);
    storeA(0);   storeB(0);
    __syncthreads();

    unsigned long long acc2[MI / 2][4];
    #pragma unroll
    for (int i = 0; i < MI / 2; ++i)
        #pragma unroll
        for (int j = 0; j < 4; ++j) acc2[i][j] = 0ull;

    int p = 0;
    for (int k0 = kbeg; k0 < kend; k0 += 16) {
        bool more = (k0 + 16) < kend;
        if (more) { loadA(k0 + 16); loadB(k0 + 16); }
        #pragma unroll
        for (int kk = 0; kk < 16; ++kk) {
            F4U bv; bv.f = *(float4*)&Bs[p][kk][tx << 2];
            unsigned long long d0 = dup2_(bv.s[0]), d1 = dup2_(bv.s[1]);
            unsigned long long d2 = dup2_(bv.s[2]), d3 = dup2_(bv.s[3]);
            #pragma unroll
            for (int q = 0; q < MI / 4; ++q) {
                F4U av; av.f = *(float4*)&As[p][kk][ty * MI + q * 4];
                acc2[2*q  ][0] = ffma2_(av.u[0], d0, acc2[2*q  ][0]);
                acc2[2*q+1][0] = ffma2_(av.u[1], d0, acc2[2*q+1][0]);
                acc2[2*q  ][1] = ffma2_(av.u[0], d1, acc2[2*q  ][1]);
                acc2[2*q+1][1] = ffma2_(av.u[1], d1, acc2[2*q+1][1]);
                acc2[2*q  ][2] = ffma2_(av.u[0], d2, acc2[2*q  ][2]);
                acc2[2*q+1][2] = ffma2_(av.u[1], d2, acc2[2*q+1][2]);
                acc2[2*q  ][3] = ffma2_(av.u[0], d3, acc2[2*q  ][3]);
                acc2[2*q+1][3] = ffma2_(av.u[1], d3, acc2[2*q+1][3]);
            }
        }
        if (more) { storeA(p ^ 1); storeB(p ^ 1); __syncthreads(); p ^= 1; }
    }

    #pragma unroll
    for (int pr = 0; pr < MI / 2; ++pr) {
        #pragma unroll
        for (int h2 = 0; h2 < 2; ++h2) {
            int m = m0 + ty * MI + pr * 2 + h2;   // pairs are consecutive m
            #pragma unroll
            for (int jx = 0; jx < 4; ++jx) {
                int n = n0 + (tx << 2) + jx;
                U2F uv; uv.u = acc2[pr][jx];
                float v = (h2 ? uv.f.y : uv.f.x) * scale;
                size_t idx = (size_t)m * N + n;
                if (ATOMIC) {
                    atomicAdd(&P0[idx], v);
                } else if (EPI == 0) {
                    P0[idx] = v;
                } else if (EPI == 1) {          // O -> ys, err = O - target
                    P0[idx] = v;
                    P1[idx] = v - Q0[idx];
                } else {                        // c = L * (1 - hnew^2)
                    float h = Q0[idx];
                    P0[idx] = v * (1.f - h * h);
                }
            }
        }
    }
}

// NOTE: acc2[pr] packs m-offsets (2pr, 2pr+1); As float4 at q*4 gives pairs
// (4q,4q+1) -> acc2[2q] and (4q+2,4q+3) -> acc2[2q+1]. Epilogue m mapping:
// pr=2q+u covers m-offset 4q+2u+h2 -- consistent because ty*MI + pr*2 + h2
// enumerates exactly those offsets for pr in [0, MI/2).

// ---------------------------------------------------------------------------
// Launch sequence (graph-capturable: kernel launches only)
// ---------------------------------------------------------------------------
extern "C" void kernel_launch(void* const* d_in, const int* in_sizes, int n_in,
                              void* d_out, int out_size)
{
    const float* x      = (const float*)d_in[0];  // [T,B,I]
    const float* target = (const float*)d_in[1];  // [T,B,O]
    const float* h0     = (const float*)d_in[2];  // [B,H]
    const float* W_in   = (const float*)d_in[3];  // [H,I]
    const float* W_hh   = (const float*)d_in[4];  // [H,H]
    const float* W_out  = (const float*)d_in[5];  // [O,H]

    float* out   = (float*)d_out;
    float* ys    = out;                                   // [T*B, O]
    float* hf    = out + (size_t)MROWS * Oo;              // [B,H]
    float* gwout = hf + BH;                               // [O,H]
    float* gwih  = gwout + (size_t)Oo * Hh;               // [H,I]
    float* gwhh  = gwih + (size_t)Hh * Ii;                // [H,H]

    float *p_xin, *p_h, *p_err, *p_c;
    cudaGetSymbolAddress((void**)&p_xin, g_xin);
    cudaGetSymbolAddress((void**)&p_h,   g_h);
    cudaGetSymbolAddress((void**)&p_err, g_err);
    cudaGetSymbolAddress((void**)&p_c,   g_c);

    const int SMEM_SCAN = (8 + Bb) * HPAD * 4;   // 164,480 B dynamic
    cudaFuncSetAttribute(scan_fwd, cudaFuncAttributeMaxDynamicSharedMemorySize, SMEM_SCAN);

    // 0. zero split-K accumulation targets (gwout..gwhh contiguous) + g_bar
    // (kNumZero, NOT "NZERO": glibc <limits.h> defines NZERO=20 on the GPU host)
    const int kNumZero = Oo * Hh + Hh * Ii + Hh * Hh;   // 1,441,792 floats
    zero_kernel<<<256, 256>>>(gwout, kNumZero);

    // 1. Xin = X @ W_in^T            [4096,1024], K=256  (DOT)
    gemmT<128, true, true, 0, false><<<dim3(Hh / 64, MROWS / 128, 1), 256>>>(
        x, Ii, 1, W_in, Ii, 1, Hh, Ii, 1.f, p_xin, nullptr, nullptr);

    // 2. init h_all[0]
    init_kernel<<<BH / 256, 256>>>(h0);

    // 3. forward scan (persistent), writes h_all[1..T] and h_f
    scan_fwd<<<GRID_SCAN, 256, SMEM_SCAN>>>(W_hh, hf);

    // 4. O = Hnew @ W_out^T -> ys; err = O - target      [4096,128], K=1024 (DOT)
    gemmT<64, true, true, 1, false><<<dim3(Oo / 64, MROWS / 64, 1), 256>>>(
        p_h + BH, Hh, 1, W_out, Hh, 1, Oo, Hh, 1.f, ys, p_err, target);

    // 5. c = (err @ W_out) * (1 - hnew^2)                [4096,1024], K=128 (NN)
    gemmT<128, true, false, 2, false><<<dim3(Hh / 64, MROWS / 128, 1), 256>>>(
        p_err, Oo, 1, W_out, 1, Hh, Hh, Oo, 1.f, p_c, nullptr, p_h + BH);

    // 6. backward scan: c -> a (in place)
    scan_bwd<<<BH / 256, 256>>>(W_hh);

    // 7. g_wout = (1/B) * err^T @ Hnew       [128,1024], K=4096, split 8 -> 128 CTAs
    gemmT<128, false, false, 0, true><<<dim3(Hh / 64, Oo / 128, 8), 256>>>(
        p_err, 1, Oo, p_h + BH, 1, Hh, Hh, MROWS / 8, 1.f / Bb, gwout, nullptr, nullptr);

    // 8. g_wih = (1e-3/B) * a^T @ X          [1024,256], K=4096, split 4 -> 128 CTAs
    gemmT<128, false, false, 0, true><<<dim3(Ii / 64, Hh / 128, 4), 256>>>(
        p_c, 1, Hh, x, 1, Ii, Ii, MROWS / 4, 1e-3f / Bb, gwih, nullptr, nullptr);

    // 9. g_whh = (1e-5/B) * a^T @ Hprev      [1024,1024], K=4096, split 2 -> 256 CTAs
    gemmT<128, false, false, 0, true><<<dim3(Hh / 64, Hh / 128, 2), 256>>>(
        p_c, 1, Hh, p_h, 1, Hh, Hh, MROWS / 2, 1e-5f / Bb, gwhh, nullptr, nullptr);
}

// round 9
// speedup vs baseline: 2.5773x; 1.7149x over previous
#include <cuda_runtime.h>
#include <cuda_bf16.h>
#include <cstdint>

// Problem dims
#define Tt 128
#define Bb 32
#define Ii 256
#define Hh 1024
#define Oo 128
#define BH (Bb*Hh)      // 32768 floats per timestep of h
#define MROWS (Tt*Bb)   // 4096 flattened (t,b) rows

// Scratch (device globals: no allocations allowed)
__device__ float g_xin[Tt*BH];        // X @ W_in^T, [T,B,H]
__device__ float g_h[(Tt+1)*BH];      // h_all[0..T], [T+1,B,H]
__device__ float g_err[MROWS*Oo];     // err, [T*B,O]
__device__ float g_c[MROWS*Hh];       // c, then (in-place) a, [T*B,H]
__device__ unsigned g_bars[128];      // 4 group barriers, stride 32 (separate lines)

// ---------------------------------------------------------------------------
// Packed fp32x2 FMA (Blackwell FFMA2: 2 fp32 FMAs per instruction)
// ---------------------------------------------------------------------------
__device__ __forceinline__ unsigned long long ffma2_(unsigned long long a,
                                                     unsigned long long b,
                                                     unsigned long long c)
{
    unsigned long long d;
    asm("fma.rn.f32x2 %0, %1, %2, %3;" : "=l"(d) : "l"(a), "l"(b), "l"(c));
    return d;
}
__device__ __forceinline__ unsigned long long dup2_(float x)
{
    unsigned long long d;
    asm("mov.b64 %0, {%1, %1};" : "=l"(d) : "f"(x));
    return d;
}
union F4U { float4 f; unsigned long long u[2]; float s[4]; };
union U2F { unsigned long long u; float2 f; };

// ---------------------------------------------------------------------------
// cp.async helper (LDGSTS .cg: bypasses L1 -> coherent with other SMs' stores)
// ---------------------------------------------------------------------------
__device__ __forceinline__ void cp16(uint32_t saddr, const void* gptr)
{
    asm volatile("cp.async.cg.shared.global [%0], [%1], 16;\n" :: "r"(saddr), "l"(gptr));
}

// ---------------------------------------------------------------------------
// zero_kernel: grid-stride zero of split-K targets + barrier reset
// init_kernel: copy h0 into g_h[0]
// ---------------------------------------------------------------------------
__global__ void zero_kernel(float* __restrict__ p, int n)
{
    int i = blockIdx.x * blockDim.x + threadIdx.x;
    if (i < 128) g_bars[i] = 0u;
    for (; i < n; i += gridDim.x * blockDim.x) p[i] = 0.f;
}

__global__ void init_kernel(const float* __restrict__ h0)
{
    int i = blockIdx.x * blockDim.x + threadIdx.x;
    if (i < BH) g_h[i] = h0[i];
}

// ---------------------------------------------------------------------------
// Forward scan: h_{t+1} = tanh(xin_t + h_t @ W_hh^T)
// Grid = 4 batch-groups x 32 row-slices = 128 CTAs, 256 threads.
//   group g owns batches [8g, 8g+8); CTA slice s owns rows [32s, 32s+32).
// W_hh lives in REGISTERS: warp w = k-slice [128w,128w+128); lane jl = row.
//   Each thread: 128 W floats in 64 f32x2 regs, loaded once.
// Per step: stage 8 batches of h (32KB) via cp.async (2 commit groups,
//   overlapped with compute); h reads are warp-broadcast LDS (no conflicts);
//   k-slice partials reduced through an 8KB SMEM array; per-group 32-CTA
//   barrier (separate counters). Batch groups never synchronize.
// ---------------------------------------------------------------------------
__global__ void __launch_bounds__(256, 1) scan_fwd(const float* __restrict__ Whh,
                                                   float* __restrict__ hf_out)
{
    __shared__ float hs[8 * Hh];          // 32KB staged h for this group's batches
    __shared__ float part[8 * 8 * 32];    // 8KB partials [kslice][b][j]

    int tid = threadIdx.x;
    int grp = blockIdx.x >> 5;            // batch group 0..3
    int sl  = blockIdx.x & 31;            // row slice 0..31
    int jbase = sl * 32;
    int bbase = grp * 8;

    int w  = tid >> 5;                    // k-slice == warp id (0..7)
    int jl = tid & 31;                    // row within slice (lane)
    int kbase = w * 128;

    // One-time: W[jbase+jl][kbase .. kbase+128) into 64 f32x2 registers
    unsigned long long wreg[64];
    {
        const float* wr = Whh + (size_t)(jbase + jl) * Hh + kbase;
        #pragma unroll
        for (int i = 0; i < 32; ++i) {
            F4U v; v.f = *(const float4*)&wr[i * 4];
            wreg[2 * i] = v.u[0]; wreg[2 * i + 1] = v.u[1];
        }
    }

    int eb = tid >> 5;                    // epilogue batch (0..7)
    int ej = tid & 31;                    // epilogue row within slice
    uint32_t hs_base = (uint32_t)__cvta_generic_to_shared(hs);
    unsigned* bar = &g_bars[grp * 32];

    for (int t = 0; t < Tt; ++t) {
        const float* hcur = g_h + (size_t)t * BH + (size_t)bbase * Hh;

        // Stage 8*1024 floats = 2048 float4 over 256 threads; 2 commit groups
        // (batches 0..3, then 4..7) so compute overlaps the second transfer.
        #pragma unroll
        for (int r = 0; r < 4; ++r) {
            int f = tid + (r << 8);
            cp16(hs_base + (f << 4), hcur + (f << 2));
        }
        asm volatile("cp.async.commit_group;\n");
        #pragma unroll
        for (int r = 4; r < 8; ++r) {
            int f = tid + (r << 8);
            cp16(hs_base + (f << 4), hcur + (f << 2));
        }
        asm volatile("cp.async.commit_group;\n");

        float accx = g_xin[(size_t)t * BH + (size_t)(bbase + eb) * Hh + jbase + ej];

        unsigned long long acc0[8], acc1[8];   // 2 chains per batch
        #pragma unroll
        for (int b = 0; b < 8; ++b) { acc0[b] = 0ull; acc1[b] = 0ull; }

        asm volatile("cp.async.wait_group 1;\n" ::: "memory");
        __syncthreads();
        #pragma unroll
        for (int b = 0; b < 4; ++b) {
            const float* hb = hs + b * Hh + kbase;
            #pragma unroll
            for (int i = 0; i < 32; ++i) {
                F4U hv; hv.f = *(const float4*)&hb[i * 4];   // warp-broadcast
                acc0[b] = ffma2_(hv.u[0], wreg[2 * i],     acc0[b]);
                acc1[b] = ffma2_(hv.u[1], wreg[2 * i + 1], acc1[b]);
            }
        }
        asm volatile("cp.async.wait_group 0;\n" ::: "memory");
        __syncthreads();
        #pragma unroll
        for (int b = 4; b < 8; ++b) {
            const float* hb = hs + b * Hh + kbase;
            #pragma unroll
            for (int i = 0; i < 32; ++i) {
                F4U hv; hv.f = *(const float4*)&hb[i * 4];
                acc0[b] = ffma2_(hv.u[0], wreg[2 * i],     acc0[b]);
                acc1[b] = ffma2_(hv.u[1], wreg[2 * i + 1], acc1[b]);
            }
        }

        // k-slice partials -> SMEM
        #pragma unroll
        for (int b = 0; b < 8; ++b) {
            U2F a, c; a.u = acc0[b]; c.u = acc1[b];
            part[w * 256 + b * 32 + jl] = (a.f.x + a.f.y) + (c.f.x + c.f.y);
        }
        __syncthreads();

        // Reduce 8 slices; thread (eb, ej)
        float s = accx;
        #pragma unroll
        for (int ww = 0; ww < 8; ++ww) s += part[ww * 256 + eb * 32 + ej];
        float hn = tanhf(s);
        __stcg(&g_h[(size_t)(t + 1) * BH + (size_t)(bbase + eb) * Hh + jbase + ej], hn);

        if (t == Tt - 1) {
            hf_out[(bbase + eb) * Hh + jbase + ej] = hn;
            break;
        }

        // Per-group barrier (32 CTAs): release -> arrive -> spin -> acquire
        __threadfence();
        __syncthreads();
        if (tid == 0) {
            atomicAdd(bar, 1u);
            unsigned tgt = (unsigned)(t + 1) * 32;
            while (*((volatile unsigned*)bar) < tgt) { }
            __threadfence();
        }
        __syncthreads();
    }
}

// ---------------------------------------------------------------------------
// Backward scan (elementwise, parallel over (b,j)):
//   a_t = c_t + diag(W_hh)[j] * (1 - h_all[t+1]^2) * a_{t+1}, in place in g_c
// ---------------------------------------------------------------------------
__global__ void scan_bwd(const float* __restrict__ Whh)
{
    int flat = blockIdx.x * blockDim.x + threadIdx.x;  // 0..BH-1
    int j = flat & (Hh - 1);
    float dw = Whh[(size_t)j * Hh + j];
    float a = g_c[(size_t)(Tt - 1) * BH + flat];
    for (int t = Tt - 2; t >= 0; --t) {
        float h   = g_h[(size_t)(t + 1) * BH + flat];
        float php = 1.f - h * h;
        a = g_c[(size_t)t * BH + flat] + dw * php * a;
        g_c[(size_t)t * BH + flat] = a;
    }
}

// ---------------------------------------------------------------------------
// Tiled fp32 GEMM, double-buffered, fp32x2 inner: C[m,n] = scale*sum_k A*B
// Tile TM x 64 (TM = 64 or 128), 256 threads, (TM/16) x 4 micro-tile per
// thread as m-pairs in packed f32x2. One __syncthreads per k-iter.
// SPLITK via blockIdx.z (chunk length Kc) + ATOMIC epilogue into zeroed out.
// EPI: 0 plain store; 1 store + err=acc-Q0 into P1; 2 store acc*(1-Q0^2).
// ---------------------------------------------------------------------------
template<int TM, bool AKC, bool BKC, int EPI, bool ATOMIC>
__global__ void __launch_bounds__(256) gemmT(const float* __restrict__ A, int sAm, int sAk,
                                             const float* __restrict__ B, int sBn, int sBk,
                                             int N, int Kc, float scale,
                                             float* __restrict__ P0, float* __restrict__ P1,
                                             const float* __restrict__ Q0)
{
    constexpr int MI  = TM / 16;     // per-thread m extent (4 or 8)
    constexpr int NLA = TM / 64;     // A-loader iterations (1 or 2)
    __shared__ float As[2][16][TM + 4];
    __shared__ float Bs[2][16][68];
    int tid = threadIdx.x;
    int m0 = blockIdx.y * TM, n0 = blockIdx.x * 64;
    int kbeg = blockIdx.z * Kc, kend = kbeg + Kc;
    int ty = tid >> 4, tx = tid & 15;

    float4 aP[NLA], bP;
    auto loadA = [&](int k0) {
        #pragma unroll
        for (int it = 0; it < NLA; ++it) {
            int f = tid + (it << 8);
            if (AKC) { int r = f >> 2, kk = (f & 3) << 2;
                aP[it] = *(const float4*)&A[(size_t)(m0 + r) * sAm + k0 + kk]; }
            else { int kk = f / (TM / 4), r = (f % (TM / 4)) << 2;
                aP[it] = *(const float4*)&A[(size_t)(k0 + kk) * sAk + m0 + r]; }
        }
    };
    auto storeA = [&](int p) {
        #pragma unroll
        for (int it = 0; it < NLA; ++it) {
            int f = tid + (it << 8);
            if (AKC) { int r = f >> 2, kk = (f & 3) << 2;
                As[p][kk][r] = aP[it].x; As[p][kk+1][r] = aP[it].y;
                As[p][kk+2][r] = aP[it].z; As[p][kk+3][r] = aP[it].w; }
            else { int kk = f / (TM / 4), r = (f % (TM / 4)) << 2;
                *(float4*)&As[p][kk][r] = aP[it]; }
        }
    };
    auto loadB = [&](int k0) {
        if (BKC) { int r = tid >> 2, kk = (tid & 3) << 2;
            bP = *(const float4*)&B[(size_t)(n0 + r) * sBn + k0 + kk]; }
        else { int kk = tid >> 4, r = (tid & 15) << 2;
            bP = *(const float4*)&B[(size_t)(k0 + kk) * sBk + n0 + r]; }
    };
    auto storeB = [&](int p) {
        if (BKC) { int r = tid >> 2, kk = (tid & 3) << 2;
            Bs[p][kk][r] = bP.x; Bs[p][kk+1][r] = bP.y;
            Bs[p][kk+2][r] = bP.z; Bs[p][kk+3][r] = bP.w; }
        else { int kk = tid >> 4, r = (tid & 15) << 2;
            *(float4*)&Bs[p][kk][r] = bP; }
    };

    loadA(kbeg); loadB(kbeg);
    storeA(0);   storeB(0);
    __syncthreads();

    unsigned long long acc2[MI / 2][4];
    #pragma unroll
    for (int i = 0; i < MI / 2; ++i)
        #pragma unroll
        for (int j = 0; j < 4; ++j) acc2[i][j] = 0ull;

    int p = 0;
    for (int k0 = kbeg; k0 < kend; k0 += 16) {
        bool more = (k0 + 16) < kend;
        if (more) { loadA(k0 + 16); loadB(k0 + 16); }
        #pragma unroll
        for (int kk = 0; kk < 16; ++kk) {
            F4U bv; bv.f = *(float4*)&Bs[p][kk][tx << 2];
            unsigned long long d0 = dup2_(bv.s[0]), d1 = dup2_(bv.s[1]);
            unsigned long long d2 = dup2_(bv.s[2]), d3 = dup2_(bv.s[3]);
            #pragma unroll
            for (int q = 0; q < MI / 4; ++q) {
                F4U av; av.f = *(float4*)&As[p][kk][ty * MI + q * 4];
                acc2[2*q  ][0] = ffma2_(av.u[0], d0, acc2[2*q  ][0]);
                acc2[2*q+1][0] = ffma2_(av.u[1], d0, acc2[2*q+1][0]);
                acc2[2*q  ][1] = ffma2_(av.u[0], d1, acc2[2*q  ][1]);
                acc2[2*q+1][1] = ffma2_(av.u[1], d1, acc2[2*q+1][1]);
                acc2[2*q  ][2] = ffma2_(av.u[0], d2, acc2[2*q  ][2]);
                acc2[2*q+1][2] = ffma2_(av.u[1], d2, acc2[2*q+1][2]);
                acc2[2*q  ][3] = ffma2_(av.u[0], d3, acc2[2*q  ][3]);
                acc2[2*q+1][3] = ffma2_(av.u[1], d3, acc2[2*q+1][3]);
            }
        }
        if (more) { storeA(p ^ 1); storeB(p ^ 1); __syncthreads(); p ^= 1; }
    }

    // acc2[pr] holds m-offsets (2pr, 2pr+1) relative to ty*MI (pairs from the
    // float4 halves); epilogue enumerates m = m0 + ty*MI + pr*2 + h2.
    #pragma unroll
    for (int pr = 0; pr < MI / 2; ++pr) {
        #pragma unroll
        for (int h2 = 0; h2 < 2; ++h2) {
            int m = m0 + ty * MI + pr * 2 + h2;
            #pragma unroll
            for (int jx = 0; jx < 4; ++jx) {
                int n = n0 + (tx << 2) + jx;
                U2F uv; uv.u = acc2[pr][jx];
                float v = (h2 ? uv.f.y : uv.f.x) * scale;
                size_t idx = (size_t)m * N + n;
                if (ATOMIC) {
                    atomicAdd(&P0[idx], v);
                } else if (EPI == 0) {
                    P0[idx] = v;
                } else if (EPI == 1) {          // O -> ys, err = O - target
                    P0[idx] = v;
                    P1[idx] = v - Q0[idx];
                } else {                        // c = L * (1 - hnew^2)
                    float h = Q0[idx];
                    P0[idx] = v * (1.f - h * h);
                }
            }
        }
    }
}

// ---------------------------------------------------------------------------
// Launch sequence (graph-capturable: kernel launches only)
// ---------------------------------------------------------------------------
extern "C" void kernel_launch(void* const* d_in, const int* in_sizes, int n_in,
                              void* d_out, int out_size)
{
    const float* x      = (const float*)d_in[0];  // [T,B,I]
    const float* target = (const float*)d_in[1];  // [T,B,O]
    const float* h0     = (const float*)d_in[2];  // [B,H]
    const float* W_in   = (const float*)d_in[3];  // [H,I]
    const float* W_hh   = (const float*)d_in[4];  // [H,H]
    const float* W_out  = (const float*)d_in[5];  // [O,H]

    float* out   = (float*)d_out;
    float* ys    = out;                                   // [T*B, O]
    float* hf    = out + (size_t)MROWS * Oo;              // [B,H]
    float* gwout = hf + BH;                               // [O,H]
    float* gwih  = gwout + (size_t)Oo * Hh;               // [H,I]
    float* gwhh  = gwih + (size_t)Hh * Ii;                // [H,H]

    float *p_xin, *p_h, *p_err, *p_c;
    cudaGetSymbolAddress((void**)&p_xin, g_xin);
    cudaGetSymbolAddress((void**)&p_h,   g_h);
    cudaGetSymbolAddress((void**)&p_err, g_err);
    cudaGetSymbolAddress((void**)&p_c,   g_c);

    // 0. zero split-K accumulation targets (gwout..gwhh contiguous) + barriers
    // (kNumZero, NOT "NZERO": glibc <limits.h> defines NZERO=20 on the GPU host)
    const int kNumZero = Oo * Hh + Hh * Ii + Hh * Hh;   // 1,441,792 floats
    zero_kernel<<<256, 256>>>(gwout, kNumZero);

    // 1. Xin = X @ W_in^T            [4096,1024], K=256  (DOT)
    gemmT<128, true, true, 0, false><<<dim3(Hh / 64, MROWS / 128, 1), 256>>>(
        x, Ii, 1, W_in, Ii, 1, Hh, Ii, 1.f, p_xin, nullptr, nullptr);

    // 2. init h_all[0]
    init_kernel<<<BH / 256, 256>>>(h0);

    // 3. forward scan (persistent, 4 batch-groups x 32 slices)
    scan_fwd<<<128, 256>>>(W_hh, hf);

    // 4. O = Hnew @ W_out^T -> ys; err = O - target      [4096,128], K=1024 (DOT)
    gemmT<64, true, true, 1, false><<<dim3(Oo / 64, MROWS / 64, 1), 256>>>(
        p_h + BH, Hh, 1, W_out, Hh, 1, Oo, Hh, 1.f, ys, p_err, target);

    // 5. c = (err @ W_out) * (1 - hnew^2)                [4096,1024], K=128 (NN)
    gemmT<128, true, false, 2, false><<<dim3(Hh / 64, MROWS / 128, 1), 256>>>(
        p_err, Oo, 1, W_out, 1, Hh, Hh, Oo, 1.f, p_c, nullptr, p_h + BH);

    // 6. backward scan: c -> a (in place)
    scan_bwd<<<BH / 256, 256>>>(W_hh);

    // 7. g_wout = (1/B) * err^T @ Hnew       [128,1024], K=4096, split 8 -> 128 CTAs
    gemmT<128, false, false, 0, true><<<dim3(Hh / 64, Oo / 128, 8), 256>>>(
        p_err, 1, Oo, p_h + BH, 1, Hh, Hh, MROWS / 8, 1.f / Bb, gwout, nullptr, nullptr);

    // 8. g_wih = (1e-3/B) * a^T @ X          [1024,256], K=4096, split 4 -> 128 CTAs
    gemmT<128, false, false, 0, true><<<dim3(Ii / 64, Hh / 128, 4), 256>>>(
        p_c, 1, Hh, x, 1, Ii, Ii, MROWS / 4, 1e-3f / Bb, gwih, nullptr, nullptr);

    // 9. g_whh = (1e-5/B) * a^T @ Hprev      [1024,1024], K=4096, split 2 -> 256 CTAs
    gemmT<128, false, false, 0, true><<<dim3(Hh / 64, Hh / 128, 2), 256>>>(
        p_c, 1, Hh, p_h, 1, Hh, Hh, MROWS / 2, 1e-5f / Bb, gwhh, nullptr, nullptr);
}